// round 5
// baseline (speedup 1.0000x reference)
#include <cuda_runtime.h>
#include <cuda_fp16.h>
#include <cstdint>
#include <cstddef>

#define NB 4
#define NT 8
#define HWPX 4096
#define NFRM 32          // NB*NT

// ---------------- device scratch ----------------
__device__ __half g_xf16 [(size_t)NFRM * HWPX * 32];   // layer-0 conv input (BN folded, fp16, swizzled)
__device__ __half g_x2f16[(size_t)NFRM * HWPX * 32];   // layer-1 conv input (BN folded, fp16, swizzled)
__device__ __half g_w16  [2 * 9 * 128 * 32];           // input kernels  [l][tap][oc][cin'] fp16 swizzled
__device__ __half g_rw16 [2 * 9 * 128 * 32];           // recur. kernels
__device__ float  g_xz   [(size_t)NFRM * HWPX * 128];  // xz = conv(in)+bias, fp32
__device__ float  g_c    [(size_t)NB * HWPX * 32];     // cell state fp32
__device__ __half g_h16  [(size_t)NB * HWPX * 32];     // hidden state fp16 swizzled
__device__ float  g_l0   [(size_t)NFRM * HWPX * 32];   // layer-0 output fp32 (residual source)

__device__ __forceinline__ float hsig(float x) { return __saturatef(fmaf(x, 0.2f, 0.5f)); }

__device__ __forceinline__ void ldsm4(unsigned* r, unsigned saddr) {
    asm volatile("ldmatrix.sync.aligned.m8n8.x4.shared.b16 {%0,%1,%2,%3}, [%4];\n"
        : "=r"(r[0]), "=r"(r[1]), "=r"(r[2]), "=r"(r[3]) : "r"(saddr));
}
__device__ __forceinline__ void mma16816(float* d, const unsigned* a, const unsigned* b) {
    asm volatile("mma.sync.aligned.m16n8k16.row.col.f32.f16.f16.f32 "
        "{%0,%1,%2,%3}, {%4,%5,%6,%7}, {%8,%9}, {%0,%1,%2,%3};\n"
        : "+f"(d[0]), "+f"(d[1]), "+f"(d[2]), "+f"(d[3])
        : "r"(a[0]), "r"(a[1]), "r"(a[2]), "r"(a[3]), "r"(b[0]), "r"(b[1]));
}

// ---------------- prep: weights fp32 [l][3][3][cin][oc] -> fp16 [l][tap][oc][cin swizzled]
__global__ void prep_w(const float* __restrict__ ker, const float* __restrict__ rker) {
    int idx = blockIdx.x * 256 + threadIdx.x;
    if (idx >= 2 * 73728) return;
    int tsel = idx >= 73728;
    int rem  = idx - tsel * 73728;
    const float* src = tsel ? rker : ker;
    __half* dst = tsel ? g_rw16 : g_w16;
    int l   = rem / 36864;
    int r2  = rem - l * 36864;
    int tap = r2 >> 12;
    int r3  = r2 & 4095;
    int cin = r3 >> 7;
    int oc  = r3 & 127;
    int sch = (cin >> 3) ^ ((oc >> 1) & 3);
    dst[l * 36864 + tap * 4096 + oc * 32 + sch * 8 + (cin & 7)] = __float2half(src[rem]);
}

// ---------------- prep: layer-0 input, BN fold + fp16 + swizzle
__global__ void prep_x(const float* __restrict__ x, const float* __restrict__ gma,
                       const float* __restrict__ bta, const float* __restrict__ mu,
                       const float* __restrict__ var) {
    int idx = blockIdx.x * 256 + threadIdx.x;     // 32*4096*8 threads
    int p   = idx >> 3;
    int c4  = (idx & 7) << 2;
    int xcol = p & 63;
    float4 v = *reinterpret_cast<const float4*>(x + (size_t)p * 32 + c4);
    float sc[4], bb[4];
    #pragma unroll
    for (int i = 0; i < 4; ++i) {
        float g = __ldg(gma + c4 + i);
        sc[i] = g * rsqrtf(__ldg(var + c4 + i) + 1e-3f);
        bb[i] = __ldg(bta + c4 + i) - __ldg(mu + c4 + i) * sc[i];
    }
    __half2 h0 = __floats2half2_rn(fmaf(v.x, sc[0], bb[0]), fmaf(v.y, sc[1], bb[1]));
    __half2 h1 = __floats2half2_rn(fmaf(v.z, sc[2], bb[2]), fmaf(v.w, sc[3], bb[3]));
    int sch = (c4 >> 3) ^ (((xcol + 1) >> 1) & 3);
    __half* d = g_xf16 + (size_t)p * 32 + sch * 8 + (c4 & 7);
    *reinterpret_cast<__half2*>(d)     = h0;
    *reinterpret_cast<__half2*>(d + 2) = h1;
}

// ---------------- conv + fused gates ----------------
// MODE 0: layer0 input conv over 32 frames; t==0 frames run the gate epilogue
//         (h0=c0=0), others write xz = conv+bias.
// MODE 3: layer1 input conv, same but gate epilogue adds residual.
// MODE 1: layer0 recurrent step t: z = conv(h)+xz; gates; out0=h; bn->out16
// MODE 2: layer1 recurrent step t: z = conv(h)+xz; gates; outF = h + res
template<int MODE>
__global__ __launch_bounds__(256, 1)
void conv_mma(const __half* __restrict__ inp, const __half* __restrict__ wsrc,
              const float* __restrict__ bias,
              const float* __restrict__ xz, float* __restrict__ cstate,
              __half* __restrict__ hstate,
              float* __restrict__ out0, __half* __restrict__ out16,
              const float* __restrict__ res, float* __restrict__ outF,
              const float* __restrict__ g1, const float* __restrict__ be1,
              const float* __restrict__ mu1, const float* __restrict__ va1,
              float* __restrict__ xzout, int t_)
{
    constexpr bool INPUT = (MODE == 0 || MODE == 3);
    constexpr bool L0    = (MODE == 0 || MODE == 1);

    extern __shared__ __half sm[];
    __half* in_s = sm;           // 4*66*32 = 8448 halves
    __half* B_s  = sm + 8448;    // 9*128*32 = 36864 halves

    const int tid  = threadIdx.x;
    const int lane = tid & 31, w = tid >> 5;
    const int mwarp = w >> 1, nw = w & 1;
    const int gid = lane >> 2, tig = lane & 3;
    const int y0 = blockIdx.x * 2;
    const int fz = blockIdx.y;                  // frame (INPUT) or b (recurrent)
    const int b  = INPUT ? (fz >> 3) : fz;
    const int t  = INPUT ? (fz & 7) : t_;
    const int frame = INPUT ? fz : fz * NT + t_;

    const __half* inF = inp + (size_t)(INPUT ? fz : b) * (HWPX * 32);

    // stage input tile (4 rows x 66 x-padded x 32c), zeros at pads
    for (int idx = tid; idx < 1056; idx += 256) {
        int r4 = idx / 264;
        int rem = idx - r4 * 264;
        int xp = rem >> 2;
        int ch = rem & 3;
        int yy = y0 - 1 + r4;
        uint4 val = make_uint4(0u, 0u, 0u, 0u);
        if (xp >= 1 && xp <= 64 && yy >= 0 && yy < 64)
            val = *reinterpret_cast<const uint4*>(inF + ((size_t)(yy * 64 + xp - 1) << 5) + ch * 8);
        *reinterpret_cast<uint4*>(in_s + (size_t)(r4 * 66 + xp) * 32 + ch * 8) = val;
    }
    // stage weights (already laid out + swizzled)
    for (int idx = tid; idx < 4608; idx += 256)
        *reinterpret_cast<uint4*>(B_s + idx * 8) =
            *reinterpret_cast<const uint4*>(wsrc + idx * 8);
    __syncthreads();

    float acc[2][8][4];
    #pragma unroll
    for (int mt = 0; mt < 2; ++mt)
        #pragma unroll
        for (int j = 0; j < 8; ++j)
            #pragma unroll
            for (int q = 0; q < 4; ++q) acc[mt][j][q] = 0.f;

    const int ylw = mwarp >> 1;
    const int xbw = (mwarp & 1) * 32;
    const int moff  = lane & 15;
    const int kselA = lane >> 4;
    const int noffB = (lane & 7) | ((lane >> 1) & 8);
    const int kselB = (lane >> 3) & 1;

    unsigned in_base = (unsigned)__cvta_generic_to_shared(in_s);
    unsigned b_base  = (unsigned)__cvta_generic_to_shared(B_s);

    #pragma unroll
    for (int tap = 0; tap < 9; ++tap) {
        const int dy = tap / 3, dx = tap % 3;
        const int yl = ylw + dy;
        #pragma unroll
        for (int h = 0; h < 2; ++h) {
            unsigned a[2][4];
            #pragma unroll
            for (int mt = 0; mt < 2; ++mt) {
                int xq = xbw + mt * 16 + moff + dx;
                int ch = (h << 1) | kselA;
                int sch = ch ^ ((xq >> 1) & 3);
                unsigned addr = in_base + (unsigned)((((yl * 66 + xq) << 5) + (sch << 3)) << 1);
                ldsm4(a[mt], addr);
            }
            unsigned bfrag[8][2];
            #pragma unroll
            for (int p = 0; p < 4; ++p) {
                int n = p * 32 + nw * 16 + noffB;
                int kc = (h << 1) | kselB;
                int sch = kc ^ ((n >> 1) & 3);
                unsigned addr = b_base + (unsigned)(((((tap * 128 + n) << 5)) + (sch << 3)) << 1);
                unsigned r[4];
                ldsm4(r, addr);
                bfrag[2 * p][0] = r[0]; bfrag[2 * p][1] = r[1];
                bfrag[2 * p + 1][0] = r[2]; bfrag[2 * p + 1][1] = r[3];
            }
            #pragma unroll
            for (int mt = 0; mt < 2; ++mt)
                #pragma unroll
                for (int j = 0; j < 8; ++j)
                    mma16816(acc[mt][j], a[mt], bfrag[j]);
        }
    }

    const bool gatepath = (!INPUT) || (t == 0);

    // BN constants for layer-1 input production (layer-0 gate paths only)
    float sbn[2][2], bbn[2][2];
    if (L0 && gatepath) {
        #pragma unroll
        for (int sub = 0; sub < 2; ++sub) {
            int f = nw * 16 + sub * 8 + tig * 2;
            #pragma unroll
            for (int c2 = 0; c2 < 2; ++c2) {
                float g = __ldg(g1 + f + c2);
                float s = g * rsqrtf(__ldg(va1 + f + c2) + 1e-3f);
                sbn[sub][c2] = s;
                bbn[sub][c2] = __ldg(be1 + f + c2) - __ldg(mu1 + f + c2) * s;
            }
        }
    }

    #pragma unroll
    for (int mt = 0; mt < 2; ++mt) {
        #pragma unroll
        for (int r = 0; r < 2; ++r) {
            int m = mwarp * 32 + mt * 16 + r * 8 + gid;
            int xcol = m & 63;
            int pix = (y0 + (m >> 6)) * 64 + xcol;
            if (INPUT && t != 0) {
                // plain xz = conv + bias
                float* o = xzout + ((size_t)frame * HWPX + pix) * 128;
                #pragma unroll
                for (int j = 0; j < 8; ++j) {
                    int oc = (j >> 1) * 32 + nw * 16 + (j & 1) * 8 + tig * 2;
                    float2 bv = *reinterpret_cast<const float2*>(bias + oc);
                    float2 st;
                    st.x = acc[mt][j][2 * r]     + bv.x;
                    st.y = acc[mt][j][2 * r + 1] + bv.y;
                    *reinterpret_cast<float2*>(o + oc) = st;
                }
            } else if (gatepath) {
                float zi[2][2], zf[2][2], zc[2][2], zo[2][2];
                const float* zp = INPUT ? nullptr
                                        : xz + ((size_t)frame * HWPX + pix) * 128;
                #pragma unroll
                for (int j = 0; j < 8; ++j) {
                    int g = j >> 1, sub = j & 1;
                    int oc = g * 32 + nw * 16 + sub * 8 + tig * 2;
                    float2 av = INPUT ? *reinterpret_cast<const float2*>(bias + oc)
                                      : *reinterpret_cast<const float2*>(zp + oc);
                    float v0 = acc[mt][j][2 * r]     + av.x;
                    float v1 = acc[mt][j][2 * r + 1] + av.y;
                    if (g == 0)      { zi[sub][0] = v0; zi[sub][1] = v1; }
                    else if (g == 1) { zf[sub][0] = v0; zf[sub][1] = v1; }
                    else if (g == 2) { zc[sub][0] = v0; zc[sub][1] = v1; }
                    else             { zo[sub][0] = v0; zo[sub][1] = v1; }
                }
                #pragma unroll
                for (int sub = 0; sub < 2; ++sub) {
                    int f = nw * 16 + sub * 8 + tig * 2;
                    size_t ci = ((size_t)b * HWPX + pix) * 32 + f;
                    float2 cp;
                    if (t == 0) { cp.x = 0.f; cp.y = 0.f; }
                    else        cp = *reinterpret_cast<const float2*>(cstate + ci);
                    float2 cn, hv;
                    cn.x = hsig(zf[sub][0]) * cp.x + hsig(zi[sub][0]) * tanhf(zc[sub][0]);
                    cn.y = hsig(zf[sub][1]) * cp.y + hsig(zi[sub][1]) * tanhf(zc[sub][1]);
                    hv.x = hsig(zo[sub][0]) * tanhf(cn.x);
                    hv.y = hsig(zo[sub][1]) * tanhf(cn.y);
                    *reinterpret_cast<float2*>(cstate + ci) = cn;
                    int sch = (f >> 3) ^ (((xcol + 1) >> 1) & 3);
                    *reinterpret_cast<__half2*>(hstate + ((size_t)b * HWPX + pix) * 32
                                                + sch * 8 + (f & 7)) =
                        __floats2half2_rn(hv.x, hv.y);
                    size_t oo = ((size_t)frame * HWPX + pix) * 32 + f;
                    if (L0) {
                        *reinterpret_cast<float2*>(out0 + oo) = hv;
                        *reinterpret_cast<__half2*>(out16 + ((size_t)frame * HWPX + pix) * 32
                                                    + sch * 8 + (f & 7)) =
                            __floats2half2_rn(fmaf(hv.x, sbn[sub][0], bbn[sub][0]),
                                              fmaf(hv.y, sbn[sub][1], bbn[sub][1]));
                    } else {
                        float2 rv = *reinterpret_cast<const float2*>(res + oo);
                        float2 ov; ov.x = hv.x + rv.x; ov.y = hv.y + rv.y;
                        *reinterpret_cast<float2*>(outF + oo) = ov;
                    }
                }
            }
        }
    }
}

// ---------------------------------------------------------------------------
extern "C" void kernel_launch(void* const* d_in, const int* in_sizes, int n_in,
                              void* d_out, int out_size)
{
    (void)in_sizes; (void)n_in; (void)out_size;
    const float* x    = (const float*)d_in[0];
    const float* gma  = (const float*)d_in[1];
    const float* bta  = (const float*)d_in[2];
    const float* mu   = (const float*)d_in[3];
    const float* var  = (const float*)d_in[4];
    const float* ker  = (const float*)d_in[5];
    const float* rker = (const float*)d_in[6];
    const float* bias = (const float*)d_in[7];

    __half *xf16, *x2f16, *w16, *rw16, *h16;
    float *xz, *cst, *l0;
    cudaGetSymbolAddress((void**)&xf16,  g_xf16);
    cudaGetSymbolAddress((void**)&x2f16, g_x2f16);
    cudaGetSymbolAddress((void**)&w16,   g_w16);
    cudaGetSymbolAddress((void**)&rw16,  g_rw16);
    cudaGetSymbolAddress((void**)&xz,    g_xz);
    cudaGetSymbolAddress((void**)&cst,   g_c);
    cudaGetSymbolAddress((void**)&h16,   g_h16);
    cudaGetSymbolAddress((void**)&l0,    g_l0);

    const size_t SMEM = (8448 + 36864) * sizeof(__half);   // 90624 B
    cudaFuncSetAttribute((const void*)conv_mma<0>, cudaFuncAttributeMaxDynamicSharedMemorySize, (int)SMEM);
    cudaFuncSetAttribute((const void*)conv_mma<1>, cudaFuncAttributeMaxDynamicSharedMemorySize, (int)SMEM);
    cudaFuncSetAttribute((const void*)conv_mma<2>, cudaFuncAttributeMaxDynamicSharedMemorySize, (int)SMEM);
    cudaFuncSetAttribute((const void*)conv_mma<3>, cudaFuncAttributeMaxDynamicSharedMemorySize, (int)SMEM);

    prep_w<<<576, 256>>>(ker, rker);
    prep_x<<<4096, 256>>>(x, gma, bta, mu, var);

    float* outF = (float*)d_out;

    // ---- layer 0 ----
    conv_mma<0><<<dim3(32, NFRM), 256, SMEM>>>(
        xf16, w16, bias, nullptr, cst, h16, l0, x2f16, nullptr, nullptr,
        gma + 32, bta + 32, mu + 32, var + 32, xz, 0);
    for (int t = 1; t < NT; ++t)
        conv_mma<1><<<dim3(32, NB), 256, SMEM>>>(
            h16, rw16, nullptr, xz, cst, h16, l0, x2f16, nullptr, nullptr,
            gma + 32, bta + 32, mu + 32, var + 32, nullptr, t);

    // ---- layer 1 ----
    conv_mma<3><<<dim3(32, NFRM), 256, SMEM>>>(
        x2f16, w16 + 36864, bias + 128, nullptr, cst, h16, nullptr, nullptr,
        l0, outF, nullptr, nullptr, nullptr, nullptr, xz, 0);
    for (int t = 1; t < NT; ++t)
        conv_mma<2><<<dim3(32, NB), 256, SMEM>>>(
            h16, rw16 + 36864, nullptr, xz, cst, h16, nullptr, nullptr,
            l0, outF, nullptr, nullptr, nullptr, nullptr, nullptr, t);
}

// round 7
// speedup vs baseline: 1.8770x; 1.8770x over previous
#include <cuda_runtime.h>
#include <cuda_fp16.h>
#include <cstdint>
#include <cstddef>

#define NB 4
#define NT 8
#define HWPX 4096
#define NFRM 32          // NB*NT

// ---------------- device scratch ----------------
__device__ __half g_xf16 [(size_t)NFRM * HWPX * 32];   // layer-0 conv input (BN folded, fp16, swizzled)
__device__ __half g_x2f16[(size_t)NFRM * HWPX * 32];   // layer-1 conv input (BN folded, fp16, swizzled)
__device__ __half g_w16  [2 * 2 * 9 * 64 * 32];        // input kernels  [l][half][tap][oc64][cin32]
__device__ __half g_rw16 [2 * 2 * 9 * 64 * 32];        // recurrent kernels, same layout
__device__ float  g_xz   [(size_t)NFRM * HWPX * 128];  // xz = conv(in)+bias, fp32, gate-permuted layout
__device__ float  g_c    [(size_t)NB * HWPX * 32];     // cell state fp32
__device__ __half g_h16  [(size_t)NB * HWPX * 32];     // hidden state fp16 swizzled
__device__ float  g_l0   [(size_t)NFRM * HWPX * 32];   // layer-0 output fp32 (residual source)

#define WHALF 18432      // halves per (layer,half) weight slice: 9*64*32

__device__ __forceinline__ float hsig(float x) { return __saturatef(fmaf(x, 0.2f, 0.5f)); }

__device__ __forceinline__ void ldsm4(unsigned* r, unsigned saddr) {
    asm volatile("ldmatrix.sync.aligned.m8n8.x4.shared.b16 {%0,%1,%2,%3}, [%4];\n"
        : "=r"(r[0]), "=r"(r[1]), "=r"(r[2]), "=r"(r[3]) : "r"(saddr));
}
__device__ __forceinline__ void mma16816(float* d, const unsigned* a, const unsigned* b) {
    asm volatile("mma.sync.aligned.m16n8k16.row.col.f32.f16.f16.f32 "
        "{%0,%1,%2,%3}, {%4,%5,%6,%7}, {%8,%9}, {%0,%1,%2,%3};\n"
        : "+f"(d[0]), "+f"(d[1]), "+f"(d[2]), "+f"(d[3])
        : "r"(a[0]), "r"(a[1]), "r"(a[2]), "r"(a[3]), "r"(b[0]), "r"(b[1]));
}

// ---------------- prep: weights fp32 [l][3][3][cin][oc] -> fp16 gate-interleaved
// dst slice (l,half): [tap][ell 0..63][cin32 swizzled], ell = nw*32 + gate*8 + (f&7)
__global__ void prep_w(const float* __restrict__ ker, const float* __restrict__ rker) {
    int idx = blockIdx.x * 256 + threadIdx.x;
    if (idx >= 2 * 73728) return;
    int tsel = idx >= 73728;
    int rem  = idx - tsel * 73728;
    const float* src = tsel ? rker : ker;
    __half* dst = tsel ? g_rw16 : g_w16;
    int l   = rem / 36864;
    int r2  = rem - l * 36864;
    int tap = r2 >> 12;
    int r3  = r2 & 4095;
    int cin = r3 >> 7;
    int oc  = r3 & 127;
    int g   = oc >> 5;
    int f   = oc & 31;
    int half = f >> 4;
    int nw   = (f >> 3) & 1;
    int ell  = nw * 32 + g * 8 + (f & 7);
    int sch  = (cin >> 3) ^ ((ell >> 1) & 3);
    dst[(size_t)(l * 2 + half) * WHALF + tap * 2048 + ell * 32 + sch * 8 + (cin & 7)]
        = __float2half(src[rem]);
}

// ---------------- prep: layer-0 input, BN fold + fp16 + swizzle
__global__ void prep_x(const float* __restrict__ x, const float* __restrict__ gma,
                       const float* __restrict__ bta, const float* __restrict__ mu,
                       const float* __restrict__ var) {
    int idx = blockIdx.x * 256 + threadIdx.x;     // 32*4096*8 threads
    int p   = idx >> 3;
    int c4  = (idx & 7) << 2;
    int xcol = p & 63;
    float4 v = *reinterpret_cast<const float4*>(x + (size_t)p * 32 + c4);
    float sc[4], bb[4];
    #pragma unroll
    for (int i = 0; i < 4; ++i) {
        float g = __ldg(gma + c4 + i);
        sc[i] = g * rsqrtf(__ldg(var + c4 + i) + 1e-3f);
        bb[i] = __ldg(bta + c4 + i) - __ldg(mu + c4 + i) * sc[i];
    }
    __half2 h0 = __floats2half2_rn(fmaf(v.x, sc[0], bb[0]), fmaf(v.y, sc[1], bb[1]));
    __half2 h1 = __floats2half2_rn(fmaf(v.z, sc[2], bb[2]), fmaf(v.w, sc[3], bb[3]));
    int sch = (c4 >> 3) ^ (((xcol + 1) >> 1) & 3);
    __half* d = g_xf16 + (size_t)p * 32 + sch * 8 + (c4 & 7);
    *reinterpret_cast<__half2*>(d)     = h0;
    *reinterpret_cast<__half2*>(d + 2) = h1;
}

// ---------------- conv + fused gates ----------------
// Block: 256 threads, M=128 px (2 y-rows x 64), N=64 oc (gate-interleaved half nh).
// MODE 0: layer0 input conv over 32 frames; t==0 frames run gate epilogue, others write xz.
// MODE 3: layer1 input conv, same but gate epilogue adds residual.
// MODE 1: layer0 recurrent step t: z = conv(h)+xz; gates; out0=h; bn->out16
// MODE 2: layer1 recurrent step t: z = conv(h)+xz; gates; outF = h + res
template<int MODE>
__global__ __launch_bounds__(256, 2)
void conv_mma(const __half* __restrict__ inp, const __half* __restrict__ wbase,
              const float* __restrict__ bias,
              const float* __restrict__ xz, float* __restrict__ cstate,
              __half* __restrict__ hstate,
              float* __restrict__ out0, __half* __restrict__ out16,
              const float* __restrict__ res, float* __restrict__ outF,
              const float* __restrict__ g1, const float* __restrict__ be1,
              const float* __restrict__ mu1, const float* __restrict__ va1,
              float* __restrict__ xzout, int t_)
{
    constexpr bool INPUT = (MODE == 0 || MODE == 3);
    constexpr bool L0    = (MODE == 0 || MODE == 1);

    extern __shared__ __half sm[];
    __half* in_s = sm;           // 4*66*32 = 8448 halves
    __half* B_s  = sm + 8448;    // 9*64*32 = 18432 halves

    const int tid  = threadIdx.x;
    const int lane = tid & 31, w = tid >> 5;
    const int mwarp = w >> 1, nw = w & 1;
    const int gid = lane >> 2, tig = lane & 3;
    const int y0 = blockIdx.x * 2;
    const int nh = blockIdx.y;                  // oc half
    const int fz = blockIdx.z;                  // frame (INPUT) or b (recurrent)
    const int b  = INPUT ? (fz >> 3) : fz;
    const int t  = INPUT ? (fz & 7) : t_;
    const int frame = INPUT ? fz : fz * NT + t_;

    const __half* inF = inp + (size_t)(INPUT ? fz : b) * (HWPX * 32);
    const __half* wsrc = wbase + (size_t)nh * WHALF;

    // stage input tile (4 rows x 66 x-padded x 32c), zeros at pads
    for (int idx = tid; idx < 1056; idx += 256) {
        int r4 = idx / 264;
        int rem = idx - r4 * 264;
        int xp = rem >> 2;
        int ch = rem & 3;
        int yy = y0 - 1 + r4;
        uint4 val = make_uint4(0u, 0u, 0u, 0u);
        if (xp >= 1 && xp <= 64 && yy >= 0 && yy < 64)
            val = *reinterpret_cast<const uint4*>(inF + ((size_t)(yy * 64 + xp - 1) << 5) + ch * 8);
        *reinterpret_cast<uint4*>(in_s + (size_t)(r4 * 66 + xp) * 32 + ch * 8) = val;
    }
    // stage weights (pre-swizzled, contiguous slice)
    for (int idx = tid; idx < 2304; idx += 256)
        *reinterpret_cast<uint4*>(B_s + idx * 8) =
            *reinterpret_cast<const uint4*>(wsrc + idx * 8);
    __syncthreads();

    float acc[2][4][4];
    #pragma unroll
    for (int mt = 0; mt < 2; ++mt)
        #pragma unroll
        for (int j = 0; j < 4; ++j)
            #pragma unroll
            for (int q = 0; q < 4; ++q) acc[mt][j][q] = 0.f;

    const int ylw = mwarp >> 1;
    const int xbw = (mwarp & 1) * 32;
    const int moff  = lane & 15;
    const int kselA = lane >> 4;
    const int noffB = (lane & 7) | ((lane >> 1) & 8);
    const int kselB = (lane >> 3) & 1;

    unsigned in_base = (unsigned)__cvta_generic_to_shared(in_s);
    unsigned b_base  = (unsigned)__cvta_generic_to_shared(B_s);

    #pragma unroll
    for (int tap = 0; tap < 9; ++tap) {
        const int dy = tap / 3, dx = tap % 3;
        const int yl = ylw + dy;
        #pragma unroll
        for (int h = 0; h < 2; ++h) {
            unsigned a[2][4];
            #pragma unroll
            for (int mt = 0; mt < 2; ++mt) {
                int xq = xbw + mt * 16 + moff + dx;
                int ch = (h << 1) | kselA;
                int sch = ch ^ ((xq >> 1) & 3);
                unsigned addr = in_base + (unsigned)((((yl * 66 + xq) << 5) + (sch << 3)) << 1);
                ldsm4(a[mt], addr);
            }
            unsigned bfrag[4][2];
            #pragma unroll
            for (int p = 0; p < 2; ++p) {
                int n = nw * 32 + p * 16 + noffB;
                int kc = (h << 1) | kselB;
                int sch = kc ^ ((n >> 1) & 3);
                unsigned addr = b_base + (unsigned)(((((tap * 64 + n) << 5)) + (sch << 3)) << 1);
                unsigned r[4];
                ldsm4(r, addr);
                bfrag[2 * p][0] = r[0]; bfrag[2 * p][1] = r[1];
                bfrag[2 * p + 1][0] = r[2]; bfrag[2 * p + 1][1] = r[3];
            }
            #pragma unroll
            for (int mt = 0; mt < 2; ++mt)
                #pragma unroll
                for (int j = 0; j < 4; ++j)
                    mma16816(acc[mt][j], a[mt], bfrag[j]);
        }
    }

    const bool gatepath = (!INPUT) || (t == 0);
    const int f = nh * 16 + nw * 8 + tig * 2;       // this thread's f-channel pair

    // BN constants for layer-1 input production (layer-0 gate paths only)
    float sbn[2], bbn[2];
    if (L0 && gatepath) {
        #pragma unroll
        for (int c2 = 0; c2 < 2; ++c2) {
            float g = __ldg(g1 + f + c2);
            float s = g * rsqrtf(__ldg(va1 + f + c2) + 1e-3f);
            sbn[c2] = s;
            bbn[c2] = __ldg(be1 + f + c2) - __ldg(mu1 + f + c2) * s;
        }
    }

    #pragma unroll
    for (int mt = 0; mt < 2; ++mt) {
        #pragma unroll
        for (int r = 0; r < 2; ++r) {
            int m = mwarp * 32 + mt * 16 + r * 8 + gid;
            int xcol = m & 63;
            int pix = (y0 + (m >> 6)) * 64 + xcol;
            if (INPUT && t != 0) {
                // plain xz = conv + bias (gate-permuted layout)
                float* o = xzout + ((size_t)frame * HWPX + pix) * 128
                           + nh * 64 + nw * 32 + tig * 2;
                #pragma unroll
                for (int g = 0; g < 4; ++g) {
                    float2 bv = *reinterpret_cast<const float2*>(bias + g * 32 + f);
                    float2 st;
                    st.x = acc[mt][g][2 * r]     + bv.x;
                    st.y = acc[mt][g][2 * r + 1] + bv.y;
                    *reinterpret_cast<float2*>(o + g * 8) = st;
                }
            } else if (gatepath) {
                float z4[4][2];
                const float* zp = INPUT ? nullptr
                    : xz + ((size_t)frame * HWPX + pix) * 128 + nh * 64 + nw * 32 + tig * 2;
                #pragma unroll
                for (int g = 0; g < 4; ++g) {
                    float2 av = INPUT
                        ? *reinterpret_cast<const float2*>(bias + g * 32 + f)
                        : *reinterpret_cast<const float2*>(zp + g * 8);
                    z4[g][0] = acc[mt][g][2 * r]     + av.x;
                    z4[g][1] = acc[mt][g][2 * r + 1] + av.y;
                }
                size_t ci = ((size_t)b * HWPX + pix) * 32 + f;
                float2 cp;
                if (t == 0) { cp.x = 0.f; cp.y = 0.f; }
                else        cp = *reinterpret_cast<const float2*>(cstate + ci);
                float2 cn, hv;
                cn.x = hsig(z4[1][0]) * cp.x + hsig(z4[0][0]) * tanhf(z4[2][0]);
                cn.y = hsig(z4[1][1]) * cp.y + hsig(z4[0][1]) * tanhf(z4[2][1]);
                hv.x = hsig(z4[3][0]) * tanhf(cn.x);
                hv.y = hsig(z4[3][1]) * tanhf(cn.y);
                *reinterpret_cast<float2*>(cstate + ci) = cn;
                int sch = (f >> 3) ^ (((xcol + 1) >> 1) & 3);
                *reinterpret_cast<__half2*>(hstate + ((size_t)b * HWPX + pix) * 32
                                            + sch * 8 + (f & 7)) =
                    __floats2half2_rn(hv.x, hv.y);
                size_t oo = ((size_t)frame * HWPX + pix) * 32 + f;
                if (L0) {
                    *reinterpret_cast<float2*>(out0 + oo) = hv;
                    *reinterpret_cast<__half2*>(out16 + ((size_t)frame * HWPX + pix) * 32
                                                + sch * 8 + (f & 7)) =
                        __floats2half2_rn(fmaf(hv.x, sbn[0], bbn[0]),
                                          fmaf(hv.y, sbn[1], bbn[1]));
                } else {
                    float2 rv = *reinterpret_cast<const float2*>(res + oo);
                    float2 ov; ov.x = hv.x + rv.x; ov.y = hv.y + rv.y;
                    *reinterpret_cast<float2*>(outF + oo) = ov;
                }
            }
        }
    }
}

// ---------------------------------------------------------------------------
extern "C" void kernel_launch(void* const* d_in, const int* in_sizes, int n_in,
                              void* d_out, int out_size)
{
    (void)in_sizes; (void)n_in; (void)out_size;
    const float* x    = (const float*)d_in[0];
    const float* gma  = (const float*)d_in[1];
    const float* bta  = (const float*)d_in[2];
    const float* mu   = (const float*)d_in[3];
    const float* var  = (const float*)d_in[4];
    const float* ker  = (const float*)d_in[5];
    const float* rker = (const float*)d_in[6];
    const float* bias = (const float*)d_in[7];

    __half *xf16, *x2f16, *w16, *rw16, *h16;
    float *xz, *cst, *l0;
    cudaGetSymbolAddress((void**)&xf16,  g_xf16);
    cudaGetSymbolAddress((void**)&x2f16, g_x2f16);
    cudaGetSymbolAddress((void**)&w16,   g_w16);
    cudaGetSymbolAddress((void**)&rw16,  g_rw16);
    cudaGetSymbolAddress((void**)&xz,    g_xz);
    cudaGetSymbolAddress((void**)&cst,   g_c);
    cudaGetSymbolAddress((void**)&h16,   g_h16);
    cudaGetSymbolAddress((void**)&l0,    g_l0);

    const size_t SMEM = (8448 + 18432) * sizeof(__half);   // 53760 B
    cudaFuncSetAttribute((const void*)conv_mma<0>, cudaFuncAttributeMaxDynamicSharedMemorySize, (int)SMEM);
    cudaFuncSetAttribute((const void*)conv_mma<1>, cudaFuncAttributeMaxDynamicSharedMemorySize, (int)SMEM);
    cudaFuncSetAttribute((const void*)conv_mma<2>, cudaFuncAttributeMaxDynamicSharedMemorySize, (int)SMEM);
    cudaFuncSetAttribute((const void*)conv_mma<3>, cudaFuncAttributeMaxDynamicSharedMemorySize, (int)SMEM);

    prep_w<<<576, 256>>>(ker, rker);
    prep_x<<<4096, 256>>>(x, gma, bta, mu, var);

    float* outF = (float*)d_out;

    // ---- layer 0 ----
    conv_mma<0><<<dim3(32, 2, NFRM), 256, SMEM>>>(
        xf16, w16, bias, nullptr, cst, h16, l0, x2f16, nullptr, nullptr,
        gma + 32, bta + 32, mu + 32, var + 32, xz, 0);
    for (int t = 1; t < NT; ++t)
        conv_mma<1><<<dim3(32, 2, NB), 256, SMEM>>>(
            h16, rw16, nullptr, xz, cst, h16, l0, x2f16, nullptr, nullptr,
            gma + 32, bta + 32, mu + 32, var + 32, nullptr, t);

    // ---- layer 1 ----
    conv_mma<3><<<dim3(32, 2, NFRM), 256, SMEM>>>(
        x2f16, w16 + 2 * WHALF, bias + 128, nullptr, cst, h16, nullptr, nullptr,
        l0, outF, nullptr, nullptr, nullptr, nullptr, xz, 0);
    for (int t = 1; t < NT; ++t)
        conv_mma<2><<<dim3(32, 2, NB), 256, SMEM>>>(
            h16, rw16 + 2 * WHALF, nullptr, xz, cst, h16, nullptr, nullptr,
            l0, outF, nullptr, nullptr, nullptr, nullptr, nullptr, t);
}

// round 8
// speedup vs baseline: 2.0647x; 1.1000x over previous
#include <cuda_runtime.h>
#include <cuda_fp16.h>
#include <cstdint>
#include <cstddef>

#define NB 4
#define NT 8
#define HWPX 4096
#define NFRM 32          // NB*NT
#define WHALF 18432      // halves per (layer,half) weight slice: 9*64*32
#define NBLK 256u        // persistent grid size (32*2*4)

// ---------------- device scratch ----------------
__device__ __half g_xf16 [(size_t)NFRM * HWPX * 32];   // layer-0 conv input (BN folded, fp16, swizzled)
__device__ __half g_x2f16[(size_t)NFRM * HWPX * 32];   // layer-1 conv input (BN folded, fp16, swizzled)
__device__ __half g_w16  [2 * 2 * 9 * 64 * 32];        // input kernels  [l][half][tap][ell64][cin32]
__device__ __half g_rw16 [2 * 2 * 9 * 64 * 32];        // recurrent kernels, same layout
__device__ float  g_xz   [(size_t)NFRM * HWPX * 128];  // xz = conv(in)+bias, fp32, gate-permuted
__device__ __half g_h16  [(size_t)NB * HWPX * 32];     // hidden state fp16 swizzled
__device__ float  g_l0   [(size_t)NFRM * HWPX * 32];   // layer-0 output fp32 (residual source)
__device__ unsigned g_bar;                             // persistent-kernel grid barrier

__device__ __forceinline__ float hsig(float x) { return __saturatef(fmaf(x, 0.2f, 0.5f)); }

__device__ __forceinline__ void ldsm4(unsigned* r, unsigned saddr) {
    asm volatile("ldmatrix.sync.aligned.m8n8.x4.shared.b16 {%0,%1,%2,%3}, [%4];\n"
        : "=r"(r[0]), "=r"(r[1]), "=r"(r[2]), "=r"(r[3]) : "r"(saddr));
}
__device__ __forceinline__ void mma16816(float* d, const unsigned* a, const unsigned* b) {
    asm volatile("mma.sync.aligned.m16n8k16.row.col.f32.f16.f16.f32 "
        "{%0,%1,%2,%3}, {%4,%5,%6,%7}, {%8,%9}, {%0,%1,%2,%3};\n"
        : "+f"(d[0]), "+f"(d[1]), "+f"(d[2]), "+f"(d[3])
        : "r"(a[0]), "r"(a[1]), "r"(a[2]), "r"(a[3]), "r"(b[0]), "r"(b[1]));
}

// grid-wide barrier (release/acquire via g_bar). Safe: grid co-resident by construction.
__device__ __forceinline__ void grid_sync(unsigned target) {
    __syncthreads();
    if (threadIdx.x == 0) {
        __threadfence();
        atomicAdd(&g_bar, 1u);
        while (*(volatile unsigned*)&g_bar < target) __nanosleep(64);
        __threadfence();
    }
    __syncthreads();
}

__global__ void zero_bar() { g_bar = 0u; }

// ---------------- prep: weights fp32 [l][3][3][cin][oc] -> fp16 gate-interleaved
// dst slice (l,half): [tap][ell 0..63][cin32 swizzled], ell = nw*32 + gate*8 + (f&7)
__global__ void prep_w(const float* __restrict__ ker, const float* __restrict__ rker) {
    int idx = blockIdx.x * 256 + threadIdx.x;
    if (idx >= 2 * 73728) return;
    int tsel = idx >= 73728;
    int rem  = idx - tsel * 73728;
    const float* src = tsel ? rker : ker;
    __half* dst = tsel ? g_rw16 : g_w16;
    int l   = rem / 36864;
    int r2  = rem - l * 36864;
    int tap = r2 >> 12;
    int r3  = r2 & 4095;
    int cin = r3 >> 7;
    int oc  = r3 & 127;
    int g   = oc >> 5;
    int f   = oc & 31;
    int half = f >> 4;
    int nw   = (f >> 3) & 1;
    int ell  = nw * 32 + g * 8 + (f & 7);
    int sch  = (cin >> 3) ^ ((ell >> 1) & 3);
    dst[(size_t)(l * 2 + half) * WHALF + tap * 2048 + ell * 32 + sch * 8 + (cin & 7)]
        = __float2half(src[rem]);
}

// ---------------- prep: layer-0 input, BN fold + fp16 + swizzle
__global__ void prep_x(const float* __restrict__ x, const float* __restrict__ gma,
                       const float* __restrict__ bta, const float* __restrict__ mu,
                       const float* __restrict__ var) {
    int idx = blockIdx.x * 256 + threadIdx.x;     // 32*4096*8 threads
    int p   = idx >> 3;
    int c4  = (idx & 7) << 2;
    int xcol = p & 63;
    float4 v = *reinterpret_cast<const float4*>(x + (size_t)p * 32 + c4);
    float sc[4], bb[4];
    #pragma unroll
    for (int i = 0; i < 4; ++i) {
        float g = __ldg(gma + c4 + i);
        sc[i] = g * rsqrtf(__ldg(var + c4 + i) + 1e-3f);
        bb[i] = __ldg(bta + c4 + i) - __ldg(mu + c4 + i) * sc[i];
    }
    __half2 h0 = __floats2half2_rn(fmaf(v.x, sc[0], bb[0]), fmaf(v.y, sc[1], bb[1]));
    __half2 h1 = __floats2half2_rn(fmaf(v.z, sc[2], bb[2]), fmaf(v.w, sc[3], bb[3]));
    int sch = (c4 >> 3) ^ (((xcol + 1) >> 1) & 3);
    __half* d = g_xf16 + (size_t)p * 32 + sch * 8 + (c4 & 7);
    *reinterpret_cast<__half2*>(d)     = h0;
    *reinterpret_cast<__half2*>(d + 2) = h1;
}

// ---------------- shared building blocks ----------------
__device__ __forceinline__ void stage_tile(const __half* __restrict__ inF,
                                           __half* __restrict__ in_s,
                                           int tid, int y0) {
    for (int idx = tid; idx < 1056; idx += 256) {
        int r4 = idx / 264;
        int rem = idx - r4 * 264;
        int xp = rem >> 2;
        int ch = rem & 3;
        int yy = y0 - 1 + r4;
        uint4 val = make_uint4(0u, 0u, 0u, 0u);
        if (xp >= 1 && xp <= 64 && yy >= 0 && yy < 64)
            val = *reinterpret_cast<const uint4*>(inF + ((size_t)(yy * 64 + xp - 1) << 5) + ch * 8);
        *reinterpret_cast<uint4*>(in_s + (size_t)(r4 * 66 + xp) * 32 + ch * 8) = val;
    }
}

__device__ __forceinline__ void conv_mainloop(unsigned in_base, unsigned b_base,
                                              int mwarp, int nw, int lane,
                                              float acc[2][4][4]) {
    const int ylw = mwarp >> 1;
    const int xbw = (mwarp & 1) * 32;
    const int moff  = lane & 15;
    const int kselA = lane >> 4;
    const int noffB = (lane & 7) | ((lane >> 1) & 8);
    const int kselB = (lane >> 3) & 1;

    #pragma unroll
    for (int tap = 0; tap < 9; ++tap) {
        const int dy = tap / 3, dx = tap % 3;
        const int yl = ylw + dy;
        #pragma unroll
        for (int h = 0; h < 2; ++h) {
            unsigned a[2][4];
            #pragma unroll
            for (int mt = 0; mt < 2; ++mt) {
                int xq = xbw + mt * 16 + moff + dx;
                int ch = (h << 1) | kselA;
                int sch = ch ^ ((xq >> 1) & 3);
                unsigned addr = in_base + (unsigned)((((yl * 66 + xq) << 5) + (sch << 3)) << 1);
                ldsm4(a[mt], addr);
            }
            unsigned bfrag[4][2];
            #pragma unroll
            for (int p = 0; p < 2; ++p) {
                int n = nw * 32 + p * 16 + noffB;
                int kc = (h << 1) | kselB;
                int sch = kc ^ ((n >> 1) & 3);
                unsigned addr = b_base + (unsigned)(((((tap * 64 + n) << 5)) + (sch << 3)) << 1);
                unsigned r[4];
                ldsm4(r, addr);
                bfrag[2 * p][0] = r[0]; bfrag[2 * p][1] = r[1];
                bfrag[2 * p + 1][0] = r[2]; bfrag[2 * p + 1][1] = r[3];
            }
            #pragma unroll
            for (int mt = 0; mt < 2; ++mt)
                #pragma unroll
                for (int j = 0; j < 4; ++j)
                    mma16816(acc[mt][j], a[mt], bfrag[j]);
        }
    }
}

// ---------------- input conv: xz = conv(in) + bias, all frames ----------------
__global__ __launch_bounds__(256, 2)
void conv_in(const __half* __restrict__ inp, const __half* __restrict__ wbase,
             const float* __restrict__ bias, float* __restrict__ xzout)
{
    extern __shared__ __half sm[];
    __half* in_s = sm;           // 8448 halves
    __half* B_s  = sm + 8448;    // 18432 halves

    const int tid  = threadIdx.x;
    const int lane = tid & 31, w = tid >> 5;
    const int mwarp = w >> 1, nw = w & 1;
    const int gid = lane >> 2, tig = lane & 3;
    const int y0 = blockIdx.x * 2;
    const int nh = blockIdx.y;
    const int frame = blockIdx.z;

    stage_tile(inp + (size_t)frame * (HWPX * 32), in_s, tid, y0);
    const __half* wsrc = wbase + (size_t)nh * WHALF;
    for (int idx = tid; idx < 2304; idx += 256)
        *reinterpret_cast<uint4*>(B_s + idx * 8) =
            *reinterpret_cast<const uint4*>(wsrc + idx * 8);
    __syncthreads();

    float acc[2][4][4];
    #pragma unroll
    for (int mt = 0; mt < 2; ++mt)
        #pragma unroll
        for (int j = 0; j < 4; ++j)
            #pragma unroll
            for (int q = 0; q < 4; ++q) acc[mt][j][q] = 0.f;

    unsigned in_base = (unsigned)__cvta_generic_to_shared(in_s);
    unsigned b_base  = (unsigned)__cvta_generic_to_shared(B_s);
    conv_mainloop(in_base, b_base, mwarp, nw, lane, acc);

    const int f = nh * 16 + nw * 8 + tig * 2;
    #pragma unroll
    for (int mt = 0; mt < 2; ++mt) {
        #pragma unroll
        for (int r = 0; r < 2; ++r) {
            int m = mwarp * 32 + mt * 16 + r * 8 + gid;
            int pix = (y0 + (m >> 6)) * 64 + (m & 63);
            float* o = xzout + ((size_t)frame * HWPX + pix) * 128
                       + nh * 64 + nw * 32 + tig * 2;
            #pragma unroll
            for (int g = 0; g < 4; ++g) {
                float2 bv = *reinterpret_cast<const float2*>(bias + g * 32 + f);
                float2 st;
                st.x = acc[mt][g][2 * r]     + bv.x;
                st.y = acc[mt][g][2 * r + 1] + bv.y;
                *reinterpret_cast<float2*>(o + g * 8) = st;
            }
        }
    }
}

// ---------------- persistent recurrent LSTM: all 8 timesteps in one launch ----
// Block owns (y-pair, nh, b); c state lives in registers across steps.
// IS_L0: outputs h (fp32 -> out0) and bn(h) (fp16 -> out16 = layer-1 input)
// else:  outputs h + res -> outF
template<bool IS_L0>
__global__ __launch_bounds__(256, 2)
void lstm_persist(const __half* __restrict__ wbase, const float* __restrict__ xz,
                  __half* __restrict__ hstate,
                  float* __restrict__ out0, __half* __restrict__ out16,
                  const float* __restrict__ res, float* __restrict__ outF,
                  const float* __restrict__ g1, const float* __restrict__ be1,
                  const float* __restrict__ mu1, const float* __restrict__ va1)
{
    extern __shared__ __half sm[];
    __half* in_s = sm;
    __half* B_s  = sm + 8448;

    const int tid  = threadIdx.x;
    const int lane = tid & 31, w = tid >> 5;
    const int mwarp = w >> 1, nw = w & 1;
    const int gid = lane >> 2, tig = lane & 3;
    const int y0 = blockIdx.x * 2;
    const int nh = blockIdx.y;
    const int b  = blockIdx.z;

    // weights once
    const __half* wsrc = wbase + (size_t)nh * WHALF;
    for (int idx = tid; idx < 2304; idx += 256)
        *reinterpret_cast<uint4*>(B_s + idx * 8) =
            *reinterpret_cast<const uint4*>(wsrc + idx * 8);

    const int f = nh * 16 + nw * 8 + tig * 2;
    float sbn[2], bbn[2];
    if (IS_L0) {
        #pragma unroll
        for (int c2 = 0; c2 < 2; ++c2) {
            float g = __ldg(g1 + f + c2);
            float s = g * rsqrtf(__ldg(va1 + f + c2) + 1e-3f);
            sbn[c2] = s;
            bbn[c2] = __ldg(be1 + f + c2) - __ldg(mu1 + f + c2) * s;
        }
    }

    unsigned in_base = (unsigned)__cvta_generic_to_shared(in_s);
    unsigned b_base  = (unsigned)__cvta_generic_to_shared(B_s);

    float2 creg[2][2];
    #pragma unroll
    for (int mt = 0; mt < 2; ++mt)
        #pragma unroll
        for (int r = 0; r < 2; ++r) { creg[mt][r].x = 0.f; creg[mt][r].y = 0.f; }

    for (int t = 0; t < NT; ++t) {
        float acc[2][4][4];
        #pragma unroll
        for (int mt = 0; mt < 2; ++mt)
            #pragma unroll
            for (int j = 0; j < 4; ++j)
                #pragma unroll
                for (int q = 0; q < 4; ++q) acc[mt][j][q] = 0.f;

        if (t > 0) {
            stage_tile(hstate + (size_t)b * (HWPX * 32), in_s, tid, y0);
            __syncthreads();
            conv_mainloop(in_base, b_base, mwarp, nw, lane, acc);
        }

        const int frame = b * NT + t;
        #pragma unroll
        for (int mt = 0; mt < 2; ++mt) {
            #pragma unroll
            for (int r = 0; r < 2; ++r) {
                int m = mwarp * 32 + mt * 16 + r * 8 + gid;
                int xcol = m & 63;
                int pix = (y0 + (m >> 6)) * 64 + xcol;
                const float* zp = xz + ((size_t)frame * HWPX + pix) * 128
                                  + nh * 64 + nw * 32 + tig * 2;
                float z4[4][2];
                #pragma unroll
                for (int g = 0; g < 4; ++g) {
                    float2 av = *reinterpret_cast<const float2*>(zp + g * 8);
                    z4[g][0] = acc[mt][g][2 * r]     + av.x;
                    z4[g][1] = acc[mt][g][2 * r + 1] + av.y;
                }
                float2 cp = creg[mt][r];
                float2 cn, hv;
                cn.x = hsig(z4[1][0]) * cp.x + hsig(z4[0][0]) * tanhf(z4[2][0]);
                cn.y = hsig(z4[1][1]) * cp.y + hsig(z4[0][1]) * tanhf(z4[2][1]);
                hv.x = hsig(z4[3][0]) * tanhf(cn.x);
                hv.y = hsig(z4[3][1]) * tanhf(cn.y);
                creg[mt][r] = cn;
                int sch = (f >> 3) ^ (((xcol + 1) >> 1) & 3);
                if (t < NT - 1)
                    *reinterpret_cast<__half2*>(hstate + ((size_t)b * HWPX + pix) * 32
                                                + sch * 8 + (f & 7)) =
                        __floats2half2_rn(hv.x, hv.y);
                size_t oo = ((size_t)frame * HWPX + pix) * 32 + f;
                if (IS_L0) {
                    *reinterpret_cast<float2*>(out0 + oo) = hv;
                    *reinterpret_cast<__half2*>(out16 + ((size_t)frame * HWPX + pix) * 32
                                                + sch * 8 + (f & 7)) =
                        __floats2half2_rn(fmaf(hv.x, sbn[0], bbn[0]),
                                          fmaf(hv.y, sbn[1], bbn[1]));
                } else {
                    float2 rv = *reinterpret_cast<const float2*>(res + oo);
                    float2 ov; ov.x = hv.x + rv.x; ov.y = hv.y + rv.y;
                    *reinterpret_cast<float2*>(outF + oo) = ov;
                }
            }
        }
        if (t < NT - 1) grid_sync(NBLK * (unsigned)(t + 1));
    }
}

// ---------------------------------------------------------------------------
extern "C" void kernel_launch(void* const* d_in, const int* in_sizes, int n_in,
                              void* d_out, int out_size)
{
    (void)in_sizes; (void)n_in; (void)out_size;
    const float* x    = (const float*)d_in[0];
    const float* gma  = (const float*)d_in[1];
    const float* bta  = (const float*)d_in[2];
    const float* mu   = (const float*)d_in[3];
    const float* var  = (const float*)d_in[4];
    const float* ker  = (const float*)d_in[5];
    const float* rker = (const float*)d_in[6];
    const float* bias = (const float*)d_in[7];

    __half *xf16, *x2f16, *w16, *rw16, *h16;
    float *xz, *l0;
    cudaGetSymbolAddress((void**)&xf16,  g_xf16);
    cudaGetSymbolAddress((void**)&x2f16, g_x2f16);
    cudaGetSymbolAddress((void**)&w16,   g_w16);
    cudaGetSymbolAddress((void**)&rw16,  g_rw16);
    cudaGetSymbolAddress((void**)&xz,    g_xz);
    cudaGetSymbolAddress((void**)&h16,   g_h16);
    cudaGetSymbolAddress((void**)&l0,    g_l0);

    const size_t SMEM = (8448 + 18432) * sizeof(__half);   // 53760 B
    cudaFuncSetAttribute((const void*)conv_in,
                         cudaFuncAttributeMaxDynamicSharedMemorySize, (int)SMEM);
    cudaFuncSetAttribute((const void*)lstm_persist<true>,
                         cudaFuncAttributeMaxDynamicSharedMemorySize, (int)SMEM);
    cudaFuncSetAttribute((const void*)lstm_persist<false>,
                         cudaFuncAttributeMaxDynamicSharedMemorySize, (int)SMEM);

    prep_w<<<576, 256>>>(ker, rker);
    prep_x<<<4096, 256>>>(x, gma, bta, mu, var);

    float* outF = (float*)d_out;

    // ---- layer 0 ----
    conv_in<<<dim3(32, 2, NFRM), 256, SMEM>>>(xf16, w16, bias, xz);
    zero_bar<<<1, 1>>>();
    lstm_persist<true><<<dim3(32, 2, NB), 256, SMEM>>>(
        rw16, xz, h16, l0, x2f16, nullptr, nullptr,
        gma + 32, bta + 32, mu + 32, var + 32);

    // ---- layer 1 ----
    conv_in<<<dim3(32, 2, NFRM), 256, SMEM>>>(x2f16, w16 + 2 * WHALF, bias + 128, xz);
    zero_bar<<<1, 1>>>();
    lstm_persist<false><<<dim3(32, 2, NB), 256, SMEM>>>(
        rw16 + 2 * WHALF, xz, h16, nullptr, nullptr, l0, outF,
        nullptr, nullptr, nullptr, nullptr);
}